// round 16
// baseline (speedup 1.0000x reference)
#include <cuda_runtime.h>
#include <stdint.h>

// ---------------------------------------------------------------------------
// ClipperEventEncoder: LIF recurrence (tau=2, v_th=1, hard reset) ->
// conv3x3(1->4)+relu -> conv3x3(4->1)+relu -> mean over T.
//
// R16: ONE launch. The ~4.2us second-launch cost is fixed (measured
// invariant across grid 256/16 and PDL), so the conv epilogue moves into
// the streaming kernel as a LAST-BLOCK tail:
//  - all 1024 blocks run the proven LIF stream (14.4us @ 7.07 TB/s),
//    write per-word summaries + speculative output zeros, and take a
//    ticket (fence + one atomicAdd). Tickets 0..1022 exit immediately.
//  - ticket 1023 -- BY DEFINITION the last finisher, it waits for nobody
//    (unlike R8's 256 pollers) -- resets the counter, reads g_any_spike:
//    zero (this input: x ~ U[0,1) keeps v=(v+x)/2 < 1 forever, exactly in
//    fp32) -> exit; nonzero -> slow-but-correct conv over all 256 tiles
//    with Phase-A skipping, overwriting the zeros.
//  - rare path recomputes conv1 on the fly (no sh array): static smem is
//    only ~6 KB, so streaming-block occupancy is unshaped; launch_bounds
//    (128,8) pins regs <=64 -> guaranteed single wave.
// ---------------------------------------------------------------------------

#define IMG_H 512
#define IMG_W 512
#define HW (IMG_H * IMG_W)
#define T_STEPS 96
#define WPR (IMG_W / 32)                 // 16 mask words per image row
#define NWORDS (IMG_H * WPR)             // 8192 words per time step
#define NBLOCKS 1024

// Mask layout: [word][t]. Only written for words that spike (all 96 t);
// everything else stays module-load zero, which is what readers need.
__device__ uint32_t g_spike_mask[NWORDS * T_STEPS];   // 3.1 MB
// Per-word timestep summary (any_t0..31, any_t32..63, any_t64..95, 0);
// written unconditionally by every warp each run.
__device__ uint4 g_word_any4[NWORDS];                 // 128 KB
// Spike indicator (bumped by spiking warps; zero-spike input: stays 0).
__device__ unsigned int g_any_spike;
// Ticket counter: 1024 increments per execution; the ticket-1023 observer
// resets it -> every graph replay starts from 0. Deterministic.
__device__ unsigned int g_sync;

#define TILE 32
#define SREG 36          // spike region edge (TILE + 4)

__global__ void __launch_bounds__(128, 8)
snn_kernel(const float* __restrict__ x,     // [96, 512, 512]
           const float* __restrict__ w1,    // [4,1,3,3]
           const float* __restrict__ w2,    // [1,4,3,3]
           float* __restrict__ out)         // [512,512]
{
    __shared__ float    ssp[SREG][SREG + 4];   // rare path: decoded spikes
    __shared__ float    sw1[36];
    __shared__ float    sw2[36];
    __shared__ uint32_t sany[4];
    __shared__ unsigned sticket;

    const int tid   = threadIdx.x;
    const int lane  = tid & 31;

    // =====================================================================
    // Phase 1: LIF streaming pass (identical to the 14.4us/7.07TB/s k1).
    // =====================================================================
    {
        const int gw    = blockIdx.x * 4 + (tid >> 5);   // global warp id
        const int seg   = gw * 64;
        const int pxA   = seg + lane;
        const int pxB   = pxA + 32;
        const int wordA = gw * 2;
        const int wordB = wordA + 1;

        float vA = 0.0f, vB = 0.0f;
        uint32_t bitsA[3], bitsB[3];

        #pragma unroll
        for (int c = 0; c < 3; ++c) {
            uint32_t aA = 0u, aB = 0u;
            #pragma unroll
            for (int tb = 0; tb < 32; tb += 8) {
                const float* __restrict__ base = x + (size_t)(c * 32 + tb) * HW;
                float ra[8], rb[8];
                #pragma unroll
                for (int j = 0; j < 8; ++j) {
                    ra[j] = __ldcs(base + (size_t)j * HW + pxA);
                    rb[j] = __ldcs(base + (size_t)j * HW + pxB);
                }
                #pragma unroll
                for (int j = 0; j < 8; ++j) {
                    vA = vA + (ra[j] - vA) * 0.5f;           // v + (x-v)/tau
                    const uint32_t sA = (vA >= 1.0f) ? 1u : 0u;
                    aA |= sA << (tb + j);
                    if (sA) vA = 0.0f;                       // hard reset

                    vB = vB + (rb[j] - vB) * 0.5f;
                    const uint32_t sB = (vB >= 1.0f) ? 1u : 0u;
                    aB |= sB << (tb + j);
                    if (sB) vB = 0.0f;
                }
            }
            bitsA[c] = aA;
            bitsB[c] = aB;
        }

        uint32_t anyA[3], anyB[3];
        #pragma unroll
        for (int c = 0; c < 3; ++c) {
            anyA[c] = __reduce_or_sync(0xffffffffu, bitsA[c]);
            anyB[c] = __reduce_or_sync(0xffffffffu, bitsB[c]);
        }
        if (lane == 0) {
            g_word_any4[wordA] = make_uint4(anyA[0], anyA[1], anyA[2], 0u);
            g_word_any4[wordB] = make_uint4(anyB[0], anyB[1], anyB[2], 0u);
        }

        const uint32_t spA = anyA[0] | anyA[1] | anyA[2];    // warp-uniform
        const uint32_t spB = anyB[0] | anyB[1] | anyB[2];

        if (spA != 0u) {                                     // rare
            uint32_t* wA = &g_spike_mask[(size_t)wordA * T_STEPS];
            #pragma unroll 1
            for (int t = 0; t < T_STEPS; ++t) {
                const int c = t >> 5, s = t & 31;
                const uint32_t m = __ballot_sync(0xffffffffu, (bitsA[c] >> s) & 1u);
                if (lane == 0) wA[t] = m;
            }
        }
        if (spB != 0u) {                                     // rare
            uint32_t* wB = &g_spike_mask[(size_t)wordB * T_STEPS];
            #pragma unroll 1
            for (int t = 0; t < T_STEPS; ++t) {
                const int c = t >> 5, s = t & 31;
                const uint32_t m = __ballot_sync(0xffffffffu, (bitsB[c] >> s) & 1u);
                if (lane == 0) wB[t] = m;
            }
        }
        if ((spA | spB) != 0u && lane == 0) atomicAdd(&g_any_spike, 1u);

        // Speculative output zeros (rare path overwrites computed tiles).
        float2* oz = reinterpret_cast<float2*>(out + (size_t)blockIdx.x * 256);
        __stcs(&oz[tid], make_float2(0.0f, 0.0f));
    }

    // ---- ticket: publish writes, count in ---------------------------------
    __syncthreads();
    __threadfence();
    if (tid == 0) sticket = atomicAdd(&g_sync, 1u);
    __syncthreads();
    if (sticket != (unsigned)(NBLOCKS - 1)) return;   // 1023 blocks exit now

    // =====================================================================
    // Phase 2 (LAST block only; waits for nobody -- it IS the last).
    // =====================================================================
    if (tid == 0) *(volatile unsigned int*)&g_sync = 0u;   // reset for replay
    __threadfence();                                        // acquire
    if (__ldcg(&g_any_spike) == 0u) return;   // common case: zeros stand

    // ---- rare, slow-but-correct conv over all 256 tiles -------------------
    if (tid < 36) { sw1[tid] = w1[tid]; sw2[tid] = w2[tid]; }

    for (int tile = 0; tile < 256; ++tile) {
        const int x0  = (tile & 15) * TILE;
        const int y0  = (tile >> 4) * TILE;
        const int wx0 = x0 >> 5;

        __syncthreads();                  // prior tile done (incl. sany reads)
        if (tid < 4) sany[tid] = 0u;
        __syncthreads();

        // Phase A: OR halo per-word summaries (superset of the 2-px halo).
        {
            uint32_t l0 = 0u, l1 = 0u, l2 = 0u;
            for (int i = tid; i < 36 * 3; i += 128) {
                const int r   = i / 3;
                const int wxo = i % 3 - 1;
                const int gy  = y0 - 2 + r;
                const int wx  = wx0 + wxo;
                if (gy >= 0 && gy < IMG_H && wx >= 0 && wx < WPR) {
                    const uint4 a = __ldcg(&g_word_any4[gy * WPR + wx]);
                    l0 |= a.x; l1 |= a.y; l2 |= a.z;
                }
            }
            if (l0) atomicOr(&sany[0], l0);
            if (l1) atomicOr(&sany[1], l1);
            if (l2) atomicOr(&sany[2], l2);
        }
        __syncthreads();

        const uint32_t a0 = sany[0], a1 = sany[1], a2 = sany[2];
        if (!(a0 | a1 | a2)) continue;    // zeros already in place

        float acc[8];
        #pragma unroll
        for (int k = 0; k < 8; ++k) acc[k] = 0.0f;

        for (int t = 0; t < T_STEPS; ++t) {
            const uint32_t chunk = (t < 32) ? a0 : (t < 64) ? a1 : a2;
            if (!((chunk >> (t & 31)) & 1u)) continue;

            // decode spike bits -> float tile (zero-padded at image edges)
            for (int i = tid; i < SREG * SREG; i += 128) {
                const int yy = i / SREG, xx = i % SREG;
                const int gy = y0 - 2 + yy, gx = x0 - 2 + xx;
                float s = 0.0f;
                if (gy >= 0 && gy < IMG_H && gx >= 0 && gx < IMG_W) {
                    const int w = gy * WPR + (gx >> 5);
                    const uint32_t m = __ldcg(&g_spike_mask[(size_t)w * T_STEPS + t]);
                    s = ((m >> (gx & 31)) & 1u) ? 1.0f : 0.0f;
                }
                ssp[yy][xx] = s;
            }
            __syncthreads();

            // conv2(relu(conv1(s))) computed on the fly (8 outputs/thread)
            #pragma unroll
            for (int k = 0; k < 8; ++k) {
                const int o  = tid + 128 * k;
                const int ly = o >> 5;
                const int lx = o & 31;
                float a = 0.0f;
                #pragma unroll
                for (int c = 0; c < 4; ++c) {
                    #pragma unroll
                    for (int ky = 0; ky < 3; ++ky) {
                        #pragma unroll
                        for (int kx = 0; kx < 3; ++kx) {
                            float h = 0.0f;
                            #pragma unroll
                            for (int jy = 0; jy < 3; ++jy) {
                                #pragma unroll
                                for (int jx = 0; jx < 3; ++jx) {
                                    h += sw1[c * 9 + jy * 3 + jx] *
                                         ssp[ly + ky + jy][lx + kx + jx];
                                }
                            }
                            a += sw2[c * 9 + ky * 3 + kx] * fmaxf(h, 0.0f);
                        }
                    }
                }
                acc[k] += fmaxf(a, 0.0f);
            }
            __syncthreads();   // ssp reuse next step
        }

        // mean over T; overwrite the speculative zeros for this tile
        const float inv_t = 1.0f / (float)T_STEPS;
        #pragma unroll
        for (int k = 0; k < 8; ++k) {
            const int o  = tid + 128 * k;
            const int ly = o >> 5;
            const int lx = o & 31;
            out[(size_t)(y0 + ly) * IMG_W + (x0 + lx)] = acc[k] * inv_t;
        }
    }
}

// ---------------------------------------------------------------------------
extern "C" void kernel_launch(void* const* d_in, const int* in_sizes, int n_in,
                              void* d_out, int out_size)
{
    const float* x_seq = (const float*)d_in[0];   // [96, 512, 512] fp32
    const float* w1    = (const float*)d_in[1];   // [4,1,3,3] fp32
    const float* w2    = (const float*)d_in[2];   // [1,4,3,3] fp32
    float*       out   = (float*)d_out;           // [512,512] fp32

    snn_kernel<<<NBLOCKS, 128>>>(x_seq, w1, w2, out);
}

// round 17
// speedup vs baseline: 1.0419x; 1.0419x over previous
#include <cuda_runtime.h>
#include <stdint.h>

// ---------------------------------------------------------------------------
// ClipperEventEncoder: LIF recurrence (tau=2, v_th=1, hard reset) ->
// conv3x3(1->4)+relu -> conv3x3(4->1)+relu -> mean over T.
//
// R17: ONE launch, phases isolated in __noinline__ functions.
// Theory: every fused attempt lost ~35% streaming BW vs the standalone k1
// (R16: 4.5 vs 7.0 TB/s, same loop, same regs/grid, no spinners, no smem
// shaping) -- the remaining difference is compile-unit blending: ptxas
// scheduling Phase 1 under a register budget shared with the big conv
// tail breaks the 16-load front-batching (MLP 16 -> ~8). __noinline__
// gives each phase its own allocation/schedule.
//  - blocks 0..1023: lif_stream() == the proven k1 (2 px/thread, 16-load
//    batches, summaries + speculative output zeros, rare-path masks),
//    then fence + ticket. Single wave (1025 blocks < 1184 slots @8/SM).
//  - block 1024: ONE waiter. Spins until all 1024 arrive (they are all
//    resident and running -> no deadlock), resets the counter
//    (deterministic graph replays), gates on g_any_spike: zero (this
//    input: x ~ U[0,1) keeps v=(v+x)/2 < 1 forever, exactly in fp32:
//    near threshold x-v is Sterbenz-exact, sum <= 1-2^-24) -> exit.
//    Spiky fallback: slow-but-correct 256-tile conv with Phase-A
//    skipping, overwriting the zeros.
// ---------------------------------------------------------------------------

#define IMG_H 512
#define IMG_W 512
#define HW (IMG_H * IMG_W)
#define T_STEPS 96
#define WPR (IMG_W / 32)                 // 16 mask words per image row
#define NWORDS (IMG_H * WPR)             // 8192 words per time step
#define NBLOCKS 1024                     // streaming blocks (+1 waiter)

// Mask layout: [word][t]. Only written for words that spike (all 96 t);
// everything else stays module-load zero, which is what readers need.
__device__ uint32_t g_spike_mask[NWORDS * T_STEPS];   // 3.1 MB
// Per-word timestep summary (any_t0..31, any_t32..63, any_t64..95, 0);
// written unconditionally by every warp each run.
__device__ uint4 g_word_any4[NWORDS];                 // 128 KB
// Spike indicator (bumped by spiking warps; zero-spike input: stays 0).
__device__ unsigned int g_any_spike;
// Ticket counter: 1024 increments per execution; the waiter resets it.
__device__ unsigned int g_sync;

#define TILE 32
#define SREG 36          // spike region edge (TILE + 4)

// ---------------------------------------------------------------------------
// Phase 1 (cold-isolated): the proven 7-TB/s LIF stream.
// ---------------------------------------------------------------------------
__device__ __noinline__ void lif_stream(const float* __restrict__ x,
                                        float* __restrict__ out,
                                        int bid, int tid)
{
    const int lane  = tid & 31;
    const int gw    = bid * 4 + (tid >> 5);          // global warp id
    const int seg   = gw * 64;
    const int pxA   = seg + lane;
    const int pxB   = pxA + 32;
    const int wordA = gw * 2;
    const int wordB = wordA + 1;

    float vA = 0.0f, vB = 0.0f;
    uint32_t bitsA[3], bitsB[3];

    // Fully unrolled: compile-time shifts; 16-load register batches.
    #pragma unroll
    for (int c = 0; c < 3; ++c) {
        uint32_t aA = 0u, aB = 0u;
        #pragma unroll
        for (int tb = 0; tb < 32; tb += 8) {
            const float* __restrict__ base = x + (size_t)(c * 32 + tb) * HW;
            float ra[8], rb[8];
            #pragma unroll
            for (int j = 0; j < 8; ++j) {
                ra[j] = __ldcs(base + (size_t)j * HW + pxA);
                rb[j] = __ldcs(base + (size_t)j * HW + pxB);
            }
            #pragma unroll
            for (int j = 0; j < 8; ++j) {
                vA = vA + (ra[j] - vA) * 0.5f;               // v + (x-v)/tau
                const uint32_t sA = (vA >= 1.0f) ? 1u : 0u;
                aA |= sA << (tb + j);
                if (sA) vA = 0.0f;                           // hard reset

                vB = vB + (rb[j] - vB) * 0.5f;
                const uint32_t sB = (vB >= 1.0f) ? 1u : 0u;
                aB |= sB << (tb + j);
                if (sB) vB = 0.0f;
            }
        }
        bitsA[c] = aA;
        bitsB[c] = aB;
    }

    uint32_t anyA[3], anyB[3];
    #pragma unroll
    for (int c = 0; c < 3; ++c) {
        anyA[c] = __reduce_or_sync(0xffffffffu, bitsA[c]);
        anyB[c] = __reduce_or_sync(0xffffffffu, bitsB[c]);
    }
    if (lane == 0) {
        g_word_any4[wordA] = make_uint4(anyA[0], anyA[1], anyA[2], 0u);
        g_word_any4[wordB] = make_uint4(anyB[0], anyB[1], anyB[2], 0u);
    }

    const uint32_t spA = anyA[0] | anyA[1] | anyA[2];        // warp-uniform
    const uint32_t spB = anyB[0] | anyB[1] | anyB[2];

    if (spA != 0u) {                                         // rare
        uint32_t* wA = &g_spike_mask[(size_t)wordA * T_STEPS];
        #pragma unroll 1
        for (int t = 0; t < T_STEPS; ++t) {
            const int c = t >> 5, s = t & 31;
            const uint32_t m = __ballot_sync(0xffffffffu, (bitsA[c] >> s) & 1u);
            if (lane == 0) wA[t] = m;
        }
    }
    if (spB != 0u) {                                         // rare
        uint32_t* wB = &g_spike_mask[(size_t)wordB * T_STEPS];
        #pragma unroll 1
        for (int t = 0; t < T_STEPS; ++t) {
            const int c = t >> 5, s = t & 31;
            const uint32_t m = __ballot_sync(0xffffffffu, (bitsB[c] >> s) & 1u);
            if (lane == 0) wB[t] = m;
        }
    }
    if ((spA | spB) != 0u && lane == 0) atomicAdd(&g_any_spike, 1u);

    // Speculative output zeros (conv tail overwrites computed tiles).
    float2* oz = reinterpret_cast<float2*>(out + (size_t)bid * 256);
    __stcs(&oz[tid], make_float2(0.0f, 0.0f));
}

// ---------------------------------------------------------------------------
// Phase 2 (cold-isolated): waiter + gate + rare conv fallback.
// ---------------------------------------------------------------------------
__device__ __noinline__ void conv_tail(const float* __restrict__ w1,
                                       const float* __restrict__ w2,
                                       float* __restrict__ out,
                                       int tid)
{
    __shared__ float    ssp[SREG][SREG + 4];
    __shared__ float    sw1[36];
    __shared__ float    sw2[36];
    __shared__ uint32_t sany[4];

    // Wait for all 1024 streaming blocks (all resident & running).
    if (tid == 0) {
        while (*(volatile unsigned int*)&g_sync < (unsigned)NBLOCKS)
            __nanosleep(64);
        *(volatile unsigned int*)&g_sync = 0u;     // reset for next replay
    }
    __syncthreads();
    __threadfence();                               // acquire streamers' writes

    if (__ldcg(&g_any_spike) == 0u) return;        // common: zeros stand

    // ---- rare, slow-but-correct conv over all 256 tiles -------------------
    if (tid < 36) { sw1[tid] = w1[tid]; sw2[tid] = w2[tid]; }

    for (int tile = 0; tile < 256; ++tile) {
        const int x0  = (tile & 15) * TILE;
        const int y0  = (tile >> 4) * TILE;
        const int wx0 = x0 >> 5;

        __syncthreads();                 // prior tile done (incl. sany reads)
        if (tid < 4) sany[tid] = 0u;
        __syncthreads();

        // Phase A: OR halo per-word summaries (superset of the 2-px halo).
        {
            uint32_t l0 = 0u, l1 = 0u, l2 = 0u;
            for (int i = tid; i < 36 * 3; i += 128) {
                const int r   = i / 3;
                const int wxo = i % 3 - 1;
                const int gy  = y0 - 2 + r;
                const int wx  = wx0 + wxo;
                if (gy >= 0 && gy < IMG_H && wx >= 0 && wx < WPR) {
                    const uint4 a = __ldcg(&g_word_any4[gy * WPR + wx]);
                    l0 |= a.x; l1 |= a.y; l2 |= a.z;
                }
            }
            if (l0) atomicOr(&sany[0], l0);
            if (l1) atomicOr(&sany[1], l1);
            if (l2) atomicOr(&sany[2], l2);
        }
        __syncthreads();

        const uint32_t a0 = sany[0], a1 = sany[1], a2 = sany[2];
        if (!(a0 | a1 | a2)) continue;   // zeros already in place

        float acc[8];
        #pragma unroll
        for (int k = 0; k < 8; ++k) acc[k] = 0.0f;

        for (int t = 0; t < T_STEPS; ++t) {
            const uint32_t chunk = (t < 32) ? a0 : (t < 64) ? a1 : a2;
            if (!((chunk >> (t & 31)) & 1u)) continue;

            // decode spike bits -> float tile (zero-padded at image edges)
            for (int i = tid; i < SREG * SREG; i += 128) {
                const int yy = i / SREG, xx = i % SREG;
                const int gy = y0 - 2 + yy, gx = x0 - 2 + xx;
                float s = 0.0f;
                if (gy >= 0 && gy < IMG_H && gx >= 0 && gx < IMG_W) {
                    const int w = gy * WPR + (gx >> 5);
                    const uint32_t m = __ldcg(&g_spike_mask[(size_t)w * T_STEPS + t]);
                    s = ((m >> (gx & 31)) & 1u) ? 1.0f : 0.0f;
                }
                ssp[yy][xx] = s;
            }
            __syncthreads();

            // conv2(relu(conv1(s))) computed on the fly (8 outputs/thread)
            #pragma unroll
            for (int k = 0; k < 8; ++k) {
                const int o  = tid + 128 * k;
                const int ly = o >> 5;
                const int lx = o & 31;
                float a = 0.0f;
                #pragma unroll
                for (int c = 0; c < 4; ++c) {
                    #pragma unroll
                    for (int ky = 0; ky < 3; ++ky) {
                        #pragma unroll
                        for (int kx = 0; kx < 3; ++kx) {
                            float h = 0.0f;
                            #pragma unroll
                            for (int jy = 0; jy < 3; ++jy) {
                                #pragma unroll
                                for (int jx = 0; jx < 3; ++jx) {
                                    h += sw1[c * 9 + jy * 3 + jx] *
                                         ssp[ly + ky + jy][lx + kx + jx];
                                }
                            }
                            a += sw2[c * 9 + ky * 3 + kx] * fmaxf(h, 0.0f);
                        }
                    }
                }
                acc[k] += fmaxf(a, 0.0f);
            }
            __syncthreads();   // ssp reuse next step
        }

        // mean over T; overwrite the speculative zeros for this tile
        const float inv_t = 1.0f / (float)T_STEPS;
        #pragma unroll
        for (int k = 0; k < 8; ++k) {
            const int o  = tid + 128 * k;
            const int ly = o >> 5;
            const int lx = o & 31;
            out[(size_t)(y0 + ly) * IMG_W + (x0 + lx)] = acc[k] * inv_t;
        }
    }
}

// ---------------------------------------------------------------------------
__global__ void __launch_bounds__(128, 8)
snn_kernel(const float* __restrict__ x,     // [96, 512, 512]
           const float* __restrict__ w1,    // [4,1,3,3]
           const float* __restrict__ w2,    // [1,4,3,3]
           float* __restrict__ out)         // [512,512]
{
    const int tid = threadIdx.x;

    if (blockIdx.x < NBLOCKS) {
        lif_stream(x, out, blockIdx.x, tid);
        // Publish this block's writes, then count in.
        __threadfence();
        __syncthreads();
        if (tid == 0) atomicAdd(&g_sync, 1u);
    } else {
        conv_tail(w1, w2, out, tid);
    }
}

// ---------------------------------------------------------------------------
extern "C" void kernel_launch(void* const* d_in, const int* in_sizes, int n_in,
                              void* d_out, int out_size)
{
    const float* x_seq = (const float*)d_in[0];   // [96, 512, 512] fp32
    const float* w1    = (const float*)d_in[1];   // [4,1,3,3] fp32
    const float* w2    = (const float*)d_in[2];   // [1,4,3,3] fp32
    float*       out   = (float*)d_out;           // [512,512] fp32

    snn_kernel<<<NBLOCKS + 1, 128>>>(x_seq, w1, w2, out);
}